// round 12
// baseline (speedup 1.0000x reference)
#include <cuda_runtime.h>
#include <cuda_bf16.h>
#include <cstdint>

// Problem constants
#define kB   8
#define kN   256
#define kM   32
#define kHW  32768

// Tiling
#define kSlabs  32
#define kSlabC  (kHW / kSlabs)   // 1024 c per CTA
#define kKC     64               // c per staged chunk
#define kChunks (kSlabC / kKC)   // 16

// ---------------------------------------------------------------------------
// Scratch (device globals: allocation-free rule)
// ---------------------------------------------------------------------------
__device__ __align__(16) float g_pX[kSlabs * kB * kM * kN];   // 8 MB  x_tgt partials [s][b][m][n]
__device__ __align__(16) float g_pS[kSlabs * kB * kM * kN];   // 8 MB  s_tgt partials
__device__ __align__(16) float g_sneg[kSlabs * kB * kN];      // softplus row-sum partials [s][b][n]
__device__ __align__(16) float g_ssum[kSlabs * kB * kN];      // sigmoid  row-sum partials
__device__ __align__(16) float g_ptsum[kSlabs * kB * kM];     // per-slab tgt row sums

// ---------------------------------------------------------------------------
// PTX helpers
// ---------------------------------------------------------------------------
__device__ __forceinline__ void ldsm_x4(uint32_t r[4], uint32_t addr) {
    asm volatile("ldmatrix.sync.aligned.m8n8.x4.shared.b16 {%0,%1,%2,%3}, [%4];"
                 : "=r"(r[0]), "=r"(r[1]), "=r"(r[2]), "=r"(r[3]) : "r"(addr));
}
__device__ __forceinline__ void ldsm_x4_t(uint32_t r[4], uint32_t addr) {
    asm volatile("ldmatrix.sync.aligned.m8n8.x4.trans.shared.b16 {%0,%1,%2,%3}, [%4];"
                 : "=r"(r[0]), "=r"(r[1]), "=r"(r[2]), "=r"(r[3]) : "r"(addr));
}
__device__ __forceinline__ void mma_bf16(float d[4], const uint32_t a[4],
                                         uint32_t b0, uint32_t b1) {
    asm volatile(
        "mma.sync.aligned.m16n8k16.row.col.f32.bf16.bf16.f32 "
        "{%0,%1,%2,%3}, {%4,%5,%6,%7}, {%8,%9}, {%0,%1,%2,%3};"
        : "+f"(d[0]), "+f"(d[1]), "+f"(d[2]), "+f"(d[3])
        : "r"(a[0]), "r"(a[1]), "r"(a[2]), "r"(a[3]), "r"(b0), "r"(b1));
}
__device__ __forceinline__ uint32_t pack_bf2(float a, float b) {
    __nv_bfloat162 t = __floats2bfloat162_rn(a, b);  // a -> low half
    return reinterpret_cast<uint32_t&>(t);
}
__device__ __forceinline__ float rcp_approx(float x) {
    float r;
    asm("rcp.approx.f32 %0, %1;" : "=f"(r) : "f"(x));
    return r;
}

// ---------------------------------------------------------------------------
// Kernel 1: fused elementwise + dual bf16 GEMM over a c-slab.
//   Register-prefetch pipeline; 3 CTAs/SM for latency hiding.
//   grid = (kSlabs, 2 n-halves, kB), block = 256 (8 warps, 16 n each)
// ---------------------------------------------------------------------------
__global__ void __launch_bounds__(256, 3)
cost_main(const float* __restrict__ heat, const float* __restrict__ tgt) {
    const int slab  = blockIdx.x;
    const int nhalf = blockIdx.y;
    const int b     = blockIdx.z;
    const int t     = threadIdx.x;
    const int lane  = t & 31;
    const int warp  = t >> 5;

    // SMEM tiles (rows padded +16B for conflict-free ldmatrix)
    __shared__ __align__(16) __nv_bfloat16 sX[kKC][136];  // [c][n] (x)
    __shared__ __align__(16) __nv_bfloat16 sS[kKC][136];  // [c][n] (sig)
    __shared__ __align__(16) __nv_bfloat16 sT[kM][72];    // [m][c] (tgt)
    __shared__ __align__(16) float         red[8][32][4][2];

    // Accumulators
    float d[2][2][2][4];  // [qty x/s][m-tile][n8][frag]
#pragma unroll
    for (int q = 0; q < 2; ++q)
#pragma unroll
        for (int mt = 0; mt < 2; ++mt)
#pragma unroll
            for (int nn = 0; nn < 2; ++nn)
#pragma unroll
                for (int k = 0; k < 4; ++k) d[q][mt][nn][k] = 0.f;
    float sneg4[4] = {0.f, 0.f, 0.f, 0.f};
    float ssum4[4] = {0.f, 0.f, 0.f, 0.f};
    float tsum_loc = 0.f;

    // Staging maps
    const int col    = t & 31;      // float4 column group -> n_local = col*4..+3
    const int rowgrp = t >> 5;      // covers c rows rowgrp*8 .. rowgrp*8+7
    const float* Xg = heat + (size_t)b * kHW * kN + nhalf * 128 + col * 4;
    const int tm = t >> 3;          // tgt row m (0..31)
    const int tc = t & 7;
    const float* Tg = tgt + ((size_t)b * kM + tm) * kHW;

    const uint32_t sx_base = (uint32_t)__cvta_generic_to_shared(&sX[0][0]);
    const uint32_t ss_base = (uint32_t)__cvta_generic_to_shared(&sS[0][0]);
    const uint32_t st_base = (uint32_t)__cvta_generic_to_shared(&sT[0][0]);

    // ldmatrix per-lane address components
    const int sub = lane & 7, grp = lane >> 3;
    const int nw  = warp * 16;  // local n offset of this warp
    const uint32_t bB_off =
        ((((grp & 1) << 3) + sub) * 136 + nw + ((grp & 2) ? 8 : 0)) * 2;
    const uint32_t aoff0 =
        ((((grp & 1) << 3) + sub) * 72 + ((grp & 2) ? 8 : 0)) * 2;
    const uint32_t aoff1 = aoff0 + 16 * 72 * 2;

    // Prefetch registers (one set; convert drains them before the next LOAD)
    float4 hreg[8];
    float4 treg[2];

    // ---- prologue: load chunk 0
    {
        const int cbase = slab * kSlabC;
#pragma unroll
        for (int i = 0; i < 8; ++i)
            hreg[i] = *reinterpret_cast<const float4*>(
                Xg + (size_t)(cbase + rowgrp * 8 + i) * kN);
#pragma unroll
        for (int j = 0; j < 2; ++j)
            treg[j] = *reinterpret_cast<const float4*>(
                Tg + cbase + ((tc * 2 + j) << 2));
    }

#pragma unroll 1
    for (int ch = 0; ch < kChunks; ++ch) {
        // ---- convert current registers -> SMEM tiles (MUFU phase)
#pragma unroll
        for (int i = 0; i < 8; ++i) {
            const int cl = rowgrp * 8 + i;
            const float xv[4] = {hreg[i].x, hreg[i].y, hreg[i].z, hreg[i].w};
            float sv[4];
#pragma unroll
            for (int k = 0; k < 4; ++k) {
                const float x = xv[k];
                const float e = __expf(-fabsf(x));
                const float r = rcp_approx(1.f + e);
                const float s = (x >= 0.f) ? r : e * r;
                const float sp = fmaxf(x, 0.f) + __logf(1.f + e);  // softplus(x)
                sneg4[k] += sp;
                ssum4[k] += s;
                sv[k] = s;
            }
            uint2 ux, us;
            ux.x = pack_bf2(xv[0], xv[1]); ux.y = pack_bf2(xv[2], xv[3]);
            us.x = pack_bf2(sv[0], sv[1]); us.y = pack_bf2(sv[2], sv[3]);
            *reinterpret_cast<uint2*>(&sX[cl][col * 4]) = ux;
            *reinterpret_cast<uint2*>(&sS[cl][col * 4]) = us;
        }
#pragma unroll
        for (int j = 0; j < 2; ++j) {
            const int c0l = (tc * 2 + j) << 2;
            const float4 v = treg[j];
            tsum_loc += (v.x + v.y) + (v.z + v.w);
            uint2 ut;
            ut.x = pack_bf2(v.x, v.y); ut.y = pack_bf2(v.z, v.w);
            *reinterpret_cast<uint2*>(&sT[tm][c0l]) = ut;
        }
        __syncthreads();

        // ---- prefetch chunk ch+1 (front-batched LDGs; hidden under MMA)
        if (ch + 1 < kChunks) {
            const int cbase = slab * kSlabC + (ch + 1) * kKC;
#pragma unroll
            for (int i = 0; i < 8; ++i)
                hreg[i] = *reinterpret_cast<const float4*>(
                    Xg + (size_t)(cbase + rowgrp * 8 + i) * kN);
#pragma unroll
            for (int j = 0; j < 2; ++j)
                treg[j] = *reinterpret_cast<const float4*>(
                    Tg + cbase + ((tc * 2 + j) << 2));
        }

        // ---- MMA: 4 k-steps of 16 c
#pragma unroll
        for (int kk = 0; kk < 4; ++kk) {
            const uint32_t koff = kk * 16;
            uint32_t afr[2][4];
            ldsm_x4(afr[0], st_base + aoff0 + koff * 2);
            ldsm_x4(afr[1], st_base + aoff1 + koff * 2);
            uint32_t bx[4], bs[4];
            const uint32_t bo = koff * 136 * 2 + bB_off;
            ldsm_x4_t(bx, sx_base + bo);
            ldsm_x4_t(bs, ss_base + bo);
#pragma unroll
            for (int mt = 0; mt < 2; ++mt)
#pragma unroll
                for (int nn = 0; nn < 2; ++nn) {
                    mma_bf16(d[0][mt][nn], afr[mt], bx[2 * nn], bx[2 * nn + 1]);
                    mma_bf16(d[1][mt][nn], afr[mt], bs[2 * nn], bs[2 * nn + 1]);
                }
        }
        __syncthreads();
    }

    // ---- write GEMM partials: pX/pS [slab][b][m][n]
    {
        const int m0   = lane >> 2;
        const int ncol = (lane & 3) * 2;
#pragma unroll
        for (int q = 0; q < 2; ++q) {
            float* pb = (q ? g_pS : g_pX) + (size_t)(slab * kB + b) * kM * kN;
#pragma unroll
            for (int mt = 0; mt < 2; ++mt)
#pragma unroll
                for (int nn = 0; nn < 2; ++nn) {
                    const int n = nhalf * 128 + nw + nn * 8 + ncol;
                    const int m = mt * 16 + m0;
                    float2 v;
                    v.x = d[q][mt][nn][0]; v.y = d[q][mt][nn][1];
                    *reinterpret_cast<float2*>(&pb[m * kN + n]) = v;
                    v.x = d[q][mt][nn][2]; v.y = d[q][mt][nn][3];
                    *reinterpret_cast<float2*>(&pb[(m + 8) * kN + n]) = v;
                }
        }
    }

    // ---- tgt row-sum partials (8 lanes per m; deterministic shfl tree)
    {
        float v = tsum_loc;
        v += __shfl_xor_sync(0xffffffffu, v, 1);
        v += __shfl_xor_sync(0xffffffffu, v, 2);
        v += __shfl_xor_sync(0xffffffffu, v, 4);
        if (nhalf == 0 && tc == 0)
            g_ptsum[(slab * kB + b) * kM + tm] = v;
    }

    // ---- deterministic row-sum reduction across the 8 row-groups
#pragma unroll
    for (int k = 0; k < 4; ++k) {
        red[rowgrp][col][k][0] = sneg4[k];
        red[rowgrp][col][k][1] = ssum4[k];
    }
    __syncthreads();
    {
        const int ocol = t >> 3, osub = (t >> 1) & 3, q = t & 1;
        float acc = 0.f;
#pragma unroll
        for (int r = 0; r < 8; ++r) acc += red[r][ocol][osub][q];
        const int ngl = nhalf * 128 + ocol * 4 + osub;
        (q ? g_ssum : g_sneg)[(slab * kB + b) * kN + ngl] = acc;
    }
}

// ---------------------------------------------------------------------------
// Kernel 2: reduce slab partials + final cost assembly
//   thread -> (b, m, n): n fastest (coalesced partial reads)
//   Explicit 16-wide register batches force high MLP (R11 had regs=32, MLP~4,
//   issue 3.7% -> pure latency stall).
// ---------------------------------------------------------------------------
__global__ void __launch_bounds__(256)
cost_epilogue(const float* __restrict__ sem, const float* __restrict__ center,
              const int* __restrict__ lw, float* __restrict__ out) {
    // Label dtype detection: int64 {0,1} labels have all-zero odd 32-bit words.
    __shared__ int s_or;
    const int tid = threadIdx.x;
    if (tid == 0) s_or = 0;
    __syncthreads();
    if (tid < 128 && lw[2 * tid + 1] != 0) atomicOr(&s_or, 1);
    __syncthreads();
    const bool is64 = (s_or == 0);

    const int g = blockIdx.x * 256 + tid;
    const int n = g & 255;
    const int m = (g >> 8) & 31;
    const int b = g >> 13;

    const int base_p = (b * kM + m) * kN + n;   // + s*kB*kM*kN
    const int base_s = b * kN + n;              // + s*kB*kN
    const int stride_p = kB * kM * kN;
    const int stride_s = kB * kN;

    float xt = 0.f, st = 0.f, sn = 0.f, ss = 0.f, ts = 0.f;
    float va[16], vb[16];

    // pX in two fully-resident batches of 16 (MLP=16)
#pragma unroll
    for (int s = 0; s < 16; ++s) va[s] = g_pX[base_p + s * stride_p];
#pragma unroll
    for (int s = 0; s < 16; ++s) vb[s] = g_pX[base_p + (s + 16) * stride_p];
#pragma unroll
    for (int s = 0; s < 16; ++s) xt += va[s] + vb[s];
    // pS
#pragma unroll
    for (int s = 0; s < 16; ++s) va[s] = g_pS[base_p + s * stride_p];
#pragma unroll
    for (int s = 0; s < 16; ++s) vb[s] = g_pS[base_p + (s + 16) * stride_p];
#pragma unroll
    for (int s = 0; s < 16; ++s) st += va[s] + vb[s];
    // sneg
#pragma unroll
    for (int s = 0; s < 16; ++s) va[s] = g_sneg[base_s + s * stride_s];
#pragma unroll
    for (int s = 0; s < 16; ++s) vb[s] = g_sneg[base_s + (s + 16) * stride_s];
#pragma unroll
    for (int s = 0; s < 16; ++s) sn += va[s] + vb[s];
    // ssum
#pragma unroll
    for (int s = 0; s < 16; ++s) va[s] = g_ssum[base_s + s * stride_s];
#pragma unroll
    for (int s = 0; s < 16; ++s) vb[s] = g_ssum[base_s + (s + 16) * stride_s];
#pragma unroll
    for (int s = 0; s < 16; ++s) ss += va[s] + vb[s];
    // ptsum (broadcast within warp; L1-hot)
#pragma unroll
    for (int s = 0; s < kSlabs; ++s) ts += g_ptsum[(s * kB + b) * kM + m];

    const int li  = b * kM + m;
    const int lbl = is64 ? lw[2 * li] : lw[li];
    const float p = sem[b * kN + n];
    const float cls   = -(lbl ? p : (1.f - p));
    const float cd    = center[(b * kN + n) * kM + m];
    const float cmask = (sn - xt) * (1.f / (float)kHW);      // Sneg - x_tgt
    const float dice  = 1.f - (2.f * st + 1.f) / (ss + ts + 1.f);

    out[(b * kN + n) * kM + m] = 2.f * cls + cd + 5.f * cmask + 2.f * dice;
}

// ---------------------------------------------------------------------------
// Entry point
// Inputs: 0 sem_cls_prob [B,N,1] f32 | 1 center_dist [B,N,M] f32
//         2 mask_heatmaps [B,HW,N] f32 | 3 mask_tgt [B,M,HW] f32
//         4 gt_plane_sem_cls_label [B,M] int (32 or 64, auto-detected)
//         5 nactual_gt (unused)
// ---------------------------------------------------------------------------
extern "C" void kernel_launch(void* const* d_in, const int* in_sizes, int n_in,
                              void* d_out, int out_size) {
    (void)in_sizes; (void)n_in; (void)out_size;
    const float* sem    = (const float*)d_in[0];
    const float* center = (const float*)d_in[1];
    const float* heat   = (const float*)d_in[2];
    const float* tgt    = (const float*)d_in[3];
    const int*   lbl    = (const int*)d_in[4];
    float* out = (float*)d_out;

    dim3 g1(kSlabs, 2, kB);
    cost_main<<<g1, 256>>>(heat, tgt);
    cost_epilogue<<<(kB * kN * kM) / 256, 256>>>(sem, center, lbl, out);
}

// round 14
// speedup vs baseline: 1.6246x; 1.6246x over previous
#include <cuda_runtime.h>
#include <cuda_bf16.h>
#include <cstdint>

// Problem constants
#define kB   8
#define kN   256
#define kM   32
#define kHW  32768

// Tiling
#define kSlabs  32
#define kSlabC  (kHW / kSlabs)   // 1024 c per CTA
#define kKC     64               // c per staged chunk
#define kChunks (kSlabC / kKC)   // 16

// ---------------------------------------------------------------------------
// Scratch (device globals: allocation-free rule)
// ---------------------------------------------------------------------------
__device__ __align__(16) float g_pX[kSlabs * kB * kM * kN];   // 8 MB  x_tgt partials [s][b][m][n]
__device__ __align__(16) float g_pS[kSlabs * kB * kM * kN];   // 8 MB  s_tgt partials
__device__ __align__(16) float g_sneg[kSlabs * kB * kN];      // softplus row-sum partials [s][b][n]
__device__ __align__(16) float g_ssum[kSlabs * kB * kN];      // sigmoid  row-sum partials
__device__ __align__(16) float g_ptsum[kSlabs * kB * kM];     // per-slab tgt row sums

// ---------------------------------------------------------------------------
// PTX helpers
// ---------------------------------------------------------------------------
__device__ __forceinline__ void ldsm_x4(uint32_t r[4], uint32_t addr) {
    asm volatile("ldmatrix.sync.aligned.m8n8.x4.shared.b16 {%0,%1,%2,%3}, [%4];"
                 : "=r"(r[0]), "=r"(r[1]), "=r"(r[2]), "=r"(r[3]) : "r"(addr));
}
__device__ __forceinline__ void ldsm_x4_t(uint32_t r[4], uint32_t addr) {
    asm volatile("ldmatrix.sync.aligned.m8n8.x4.trans.shared.b16 {%0,%1,%2,%3}, [%4];"
                 : "=r"(r[0]), "=r"(r[1]), "=r"(r[2]), "=r"(r[3]) : "r"(addr));
}
__device__ __forceinline__ void mma_bf16(float d[4], const uint32_t a[4],
                                         uint32_t b0, uint32_t b1) {
    asm volatile(
        "mma.sync.aligned.m16n8k16.row.col.f32.bf16.bf16.f32 "
        "{%0,%1,%2,%3}, {%4,%5,%6,%7}, {%8,%9}, {%0,%1,%2,%3};"
        : "+f"(d[0]), "+f"(d[1]), "+f"(d[2]), "+f"(d[3])
        : "r"(a[0]), "r"(a[1]), "r"(a[2]), "r"(a[3]), "r"(b0), "r"(b1));
}
__device__ __forceinline__ uint32_t pack_bf2(float a, float b) {
    __nv_bfloat162 t = __floats2bfloat162_rn(a, b);  // a -> low half
    return reinterpret_cast<uint32_t&>(t);
}
__device__ __forceinline__ float rcp_approx(float x) {
    float r;
    asm("rcp.approx.f32 %0, %1;" : "=f"(r) : "f"(x));
    return r;
}

// ---------------------------------------------------------------------------
// Kernel 1: fused elementwise + dual bf16 GEMM over a c-slab.
//   Register-prefetch pipeline (R11 config: occ=2, full reg headroom — the
//   occ=3 experiment in R12 capped regs at 85 and destroyed prefetch MLP).
//   grid = (kSlabs, 2 n-halves, kB), block = 256 (8 warps, 16 n each)
// ---------------------------------------------------------------------------
__global__ void __launch_bounds__(256, 2)
cost_main(const float* __restrict__ heat, const float* __restrict__ tgt) {
    const int slab  = blockIdx.x;
    const int nhalf = blockIdx.y;
    const int b     = blockIdx.z;
    const int t     = threadIdx.x;
    const int lane  = t & 31;
    const int warp  = t >> 5;

    // SMEM tiles (rows padded +16B for conflict-free ldmatrix)
    __shared__ __align__(16) __nv_bfloat16 sX[kKC][136];  // [c][n] (x)
    __shared__ __align__(16) __nv_bfloat16 sS[kKC][136];  // [c][n] (sig)
    __shared__ __align__(16) __nv_bfloat16 sT[kM][72];    // [m][c] (tgt)
    __shared__ __align__(16) float         red[8][32][4][2];

    // Accumulators
    float d[2][2][2][4];  // [qty x/s][m-tile][n8][frag]
#pragma unroll
    for (int q = 0; q < 2; ++q)
#pragma unroll
        for (int mt = 0; mt < 2; ++mt)
#pragma unroll
            for (int nn = 0; nn < 2; ++nn)
#pragma unroll
                for (int k = 0; k < 4; ++k) d[q][mt][nn][k] = 0.f;
    float sneg4[4] = {0.f, 0.f, 0.f, 0.f};
    float ssum4[4] = {0.f, 0.f, 0.f, 0.f};
    float tsum_loc = 0.f;

    // Staging maps
    const int col    = t & 31;      // float4 column group -> n_local = col*4..+3
    const int rowgrp = t >> 5;      // covers c rows rowgrp*8 .. rowgrp*8+7
    const float* Xg = heat + (size_t)b * kHW * kN + nhalf * 128 + col * 4;
    const int tm = t >> 3;          // tgt row m (0..31)
    const int tc = t & 7;
    const float* Tg = tgt + ((size_t)b * kM + tm) * kHW;

    const uint32_t sx_base = (uint32_t)__cvta_generic_to_shared(&sX[0][0]);
    const uint32_t ss_base = (uint32_t)__cvta_generic_to_shared(&sS[0][0]);
    const uint32_t st_base = (uint32_t)__cvta_generic_to_shared(&sT[0][0]);

    // ldmatrix per-lane address components
    const int sub = lane & 7, grp = lane >> 3;
    const int nw  = warp * 16;  // local n offset of this warp
    const uint32_t bB_off =
        ((((grp & 1) << 3) + sub) * 136 + nw + ((grp & 2) ? 8 : 0)) * 2;
    const uint32_t aoff0 =
        ((((grp & 1) << 3) + sub) * 72 + ((grp & 2) ? 8 : 0)) * 2;
    const uint32_t aoff1 = aoff0 + 16 * 72 * 2;

    // Prefetch registers (one set; convert drains them before the next LOAD)
    float4 hreg[8];
    float4 treg[2];

    // ---- prologue: load chunk 0
    {
        const int cbase = slab * kSlabC;
#pragma unroll
        for (int i = 0; i < 8; ++i)
            hreg[i] = *reinterpret_cast<const float4*>(
                Xg + (size_t)(cbase + rowgrp * 8 + i) * kN);
#pragma unroll
        for (int j = 0; j < 2; ++j)
            treg[j] = *reinterpret_cast<const float4*>(
                Tg + cbase + ((tc * 2 + j) << 2));
    }

#pragma unroll 1
    for (int ch = 0; ch < kChunks; ++ch) {
        // ---- convert current registers -> SMEM tiles (MUFU phase)
#pragma unroll
        for (int i = 0; i < 8; ++i) {
            const int cl = rowgrp * 8 + i;
            const float xv[4] = {hreg[i].x, hreg[i].y, hreg[i].z, hreg[i].w};
            float sv[4];
#pragma unroll
            for (int k = 0; k < 4; ++k) {
                const float x = xv[k];
                const float e = __expf(-fabsf(x));
                const float r = rcp_approx(1.f + e);
                const float s = (x >= 0.f) ? r : e * r;
                const float sp = fmaxf(x, 0.f) + __logf(1.f + e);  // softplus(x)
                sneg4[k] += sp;
                ssum4[k] += s;
                sv[k] = s;
            }
            uint2 ux, us;
            ux.x = pack_bf2(xv[0], xv[1]); ux.y = pack_bf2(xv[2], xv[3]);
            us.x = pack_bf2(sv[0], sv[1]); us.y = pack_bf2(sv[2], sv[3]);
            *reinterpret_cast<uint2*>(&sX[cl][col * 4]) = ux;
            *reinterpret_cast<uint2*>(&sS[cl][col * 4]) = us;
        }
#pragma unroll
        for (int j = 0; j < 2; ++j) {
            const int c0l = (tc * 2 + j) << 2;
            const float4 v = treg[j];
            tsum_loc += (v.x + v.y) + (v.z + v.w);
            uint2 ut;
            ut.x = pack_bf2(v.x, v.y); ut.y = pack_bf2(v.z, v.w);
            *reinterpret_cast<uint2*>(&sT[tm][c0l]) = ut;
        }
        __syncthreads();

        // ---- prefetch chunk ch+1 (front-batched LDGs; hidden under MMA)
        if (ch + 1 < kChunks) {
            const int cbase = slab * kSlabC + (ch + 1) * kKC;
#pragma unroll
            for (int i = 0; i < 8; ++i)
                hreg[i] = *reinterpret_cast<const float4*>(
                    Xg + (size_t)(cbase + rowgrp * 8 + i) * kN);
#pragma unroll
            for (int j = 0; j < 2; ++j)
                treg[j] = *reinterpret_cast<const float4*>(
                    Tg + cbase + ((tc * 2 + j) << 2));
        }

        // ---- MMA: 4 k-steps of 16 c
#pragma unroll
        for (int kk = 0; kk < 4; ++kk) {
            const uint32_t koff = kk * 16;
            uint32_t afr[2][4];
            ldsm_x4(afr[0], st_base + aoff0 + koff * 2);
            ldsm_x4(afr[1], st_base + aoff1 + koff * 2);
            uint32_t bx[4], bs[4];
            const uint32_t bo = koff * 136 * 2 + bB_off;
            ldsm_x4_t(bx, sx_base + bo);
            ldsm_x4_t(bs, ss_base + bo);
#pragma unroll
            for (int mt = 0; mt < 2; ++mt)
#pragma unroll
                for (int nn = 0; nn < 2; ++nn) {
                    mma_bf16(d[0][mt][nn], afr[mt], bx[2 * nn], bx[2 * nn + 1]);
                    mma_bf16(d[1][mt][nn], afr[mt], bs[2 * nn], bs[2 * nn + 1]);
                }
        }
        __syncthreads();
    }

    // ---- write GEMM partials: pX/pS [slab][b][m][n]
    {
        const int m0   = lane >> 2;
        const int ncol = (lane & 3) * 2;
#pragma unroll
        for (int q = 0; q < 2; ++q) {
            float* pb = (q ? g_pS : g_pX) + (size_t)(slab * kB + b) * kM * kN;
#pragma unroll
            for (int mt = 0; mt < 2; ++mt)
#pragma unroll
                for (int nn = 0; nn < 2; ++nn) {
                    const int n = nhalf * 128 + nw + nn * 8 + ncol;
                    const int m = mt * 16 + m0;
                    float2 v;
                    v.x = d[q][mt][nn][0]; v.y = d[q][mt][nn][1];
                    *reinterpret_cast<float2*>(&pb[m * kN + n]) = v;
                    v.x = d[q][mt][nn][2]; v.y = d[q][mt][nn][3];
                    *reinterpret_cast<float2*>(&pb[(m + 8) * kN + n]) = v;
                }
        }
    }

    // ---- tgt row-sum partials (8 lanes per m; deterministic shfl tree)
    {
        float v = tsum_loc;
        v += __shfl_xor_sync(0xffffffffu, v, 1);
        v += __shfl_xor_sync(0xffffffffu, v, 2);
        v += __shfl_xor_sync(0xffffffffu, v, 4);
        if (nhalf == 0 && tc == 0)
            g_ptsum[(slab * kB + b) * kM + tm] = v;
    }

    // ---- deterministic row-sum reduction across the 8 row-groups
#pragma unroll
    for (int k = 0; k < 4; ++k) {
        red[rowgrp][col][k][0] = sneg4[k];
        red[rowgrp][col][k][1] = ssum4[k];
    }
    __syncthreads();
    {
        const int ocol = t >> 3, osub = (t >> 1) & 3, q = t & 1;
        float acc = 0.f;
#pragma unroll
        for (int r = 0; r < 8; ++r) acc += red[r][ocol][osub][q];
        const int ngl = nhalf * 128 + ocol * 4 + osub;
        (q ? g_ssum : g_sneg)[(slab * kB + b) * kN + ngl] = acc;
    }
}

// ---------------------------------------------------------------------------
// Kernel 2: reduce slab partials + final cost assembly
//   thread -> (b, m, n): n fastest (coalesced partial reads)
//   Explicit 16-wide register batches force high MLP (proven: 21.7 -> 11.8us)
// ---------------------------------------------------------------------------
__global__ void __launch_bounds__(256)
cost_epilogue(const float* __restrict__ sem, const float* __restrict__ center,
              const int* __restrict__ lw, float* __restrict__ out) {
    // Label dtype detection: int64 {0,1} labels have all-zero odd 32-bit words.
    __shared__ int s_or;
    const int tid = threadIdx.x;
    if (tid == 0) s_or = 0;
    __syncthreads();
    if (tid < 128 && lw[2 * tid + 1] != 0) atomicOr(&s_or, 1);
    __syncthreads();
    const bool is64 = (s_or == 0);

    const int g = blockIdx.x * 256 + tid;
    const int n = g & 255;
    const int m = (g >> 8) & 31;
    const int b = g >> 13;

    const int base_p = (b * kM + m) * kN + n;   // + s*kB*kM*kN
    const int base_s = b * kN + n;              // + s*kB*kN
    const int stride_p = kB * kM * kN;
    const int stride_s = kB * kN;

    float xt = 0.f, st = 0.f, sn = 0.f, ss = 0.f, ts = 0.f;
    float va[16], vb[16];

    // pX in two fully-resident batches of 16 (MLP=16)
#pragma unroll
    for (int s = 0; s < 16; ++s) va[s] = g_pX[base_p + s * stride_p];
#pragma unroll
    for (int s = 0; s < 16; ++s) vb[s] = g_pX[base_p + (s + 16) * stride_p];
#pragma unroll
    for (int s = 0; s < 16; ++s) xt += va[s] + vb[s];
    // pS
#pragma unroll
    for (int s = 0; s < 16; ++s) va[s] = g_pS[base_p + s * stride_p];
#pragma unroll
    for (int s = 0; s < 16; ++s) vb[s] = g_pS[base_p + (s + 16) * stride_p];
#pragma unroll
    for (int s = 0; s < 16; ++s) st += va[s] + vb[s];
    // sneg
#pragma unroll
    for (int s = 0; s < 16; ++s) va[s] = g_sneg[base_s + s * stride_s];
#pragma unroll
    for (int s = 0; s < 16; ++s) vb[s] = g_sneg[base_s + (s + 16) * stride_s];
#pragma unroll
    for (int s = 0; s < 16; ++s) sn += va[s] + vb[s];
    // ssum
#pragma unroll
    for (int s = 0; s < 16; ++s) va[s] = g_ssum[base_s + s * stride_s];
#pragma unroll
    for (int s = 0; s < 16; ++s) vb[s] = g_ssum[base_s + (s + 16) * stride_s];
#pragma unroll
    for (int s = 0; s < 16; ++s) ss += va[s] + vb[s];
    // ptsum (broadcast within warp; L1-hot)
#pragma unroll
    for (int s = 0; s < kSlabs; ++s) ts += g_ptsum[(s * kB + b) * kM + m];

    const int li  = b * kM + m;
    const int lbl = is64 ? lw[2 * li] : lw[li];
    const float p = sem[b * kN + n];
    const float cls   = -(lbl ? p : (1.f - p));
    const float cd    = center[(b * kN + n) * kM + m];
    const float cmask = (sn - xt) * (1.f / (float)kHW);      // Sneg - x_tgt
    const float dice  = 1.f - (2.f * st + 1.f) / (ss + ts + 1.f);

    out[(b * kN + n) * kM + m] = 2.f * cls + cd + 5.f * cmask + 2.f * dice;
}

// ---------------------------------------------------------------------------
// Entry point
// Inputs: 0 sem_cls_prob [B,N,1] f32 | 1 center_dist [B,N,M] f32
//         2 mask_heatmaps [B,HW,N] f32 | 3 mask_tgt [B,M,HW] f32
//         4 gt_plane_sem_cls_label [B,M] int (32 or 64, auto-detected)
//         5 nactual_gt (unused)
// ---------------------------------------------------------------------------
extern "C" void kernel_launch(void* const* d_in, const int* in_sizes, int n_in,
                              void* d_out, int out_size) {
    (void)in_sizes; (void)n_in; (void)out_size;
    const float* sem    = (const float*)d_in[0];
    const float* center = (const float*)d_in[1];
    const float* heat   = (const float*)d_in[2];
    const float* tgt    = (const float*)d_in[3];
    const int*   lbl    = (const int*)d_in[4];
    float* out = (float*)d_out;

    dim3 g1(kSlabs, 2, kB);
    cost_main<<<g1, 256>>>(heat, tgt);
    cost_epilogue<<<(kB * kN * kM) / 256, 256>>>(sem, center, lbl, out);
}

// round 15
// speedup vs baseline: 1.6296x; 1.0031x over previous
#include <cuda_runtime.h>
#include <cuda_bf16.h>
#include <cstdint>

// Problem constants
#define kB   8
#define kN   256
#define kM   32
#define kHW  32768

// Tiling
#define kSlabs  32
#define kSlabC  (kHW / kSlabs)   // 1024 c per CTA
#define kKC     64               // c per staged chunk
#define kChunks (kSlabC / kKC)   // 16

// ---------------------------------------------------------------------------
// Scratch (device globals: allocation-free rule)
// ---------------------------------------------------------------------------
__device__ __align__(16) float g_pX[kSlabs * kB * kM * kN];   // 8 MB  x_tgt partials [s][b][m][n]
__device__ __align__(16) float g_pS[kSlabs * kB * kM * kN];   // 8 MB  s_tgt partials
__device__ __align__(16) float g_sneg[kSlabs * kB * kN];      // softplus row-sum partials [s][b][n]
__device__ __align__(16) float g_ssum[kSlabs * kB * kN];      // sigmoid  row-sum partials
__device__ __align__(16) float g_ptsum[kSlabs * kB * kM];     // per-slab tgt row sums

// ---------------------------------------------------------------------------
// PTX helpers
// ---------------------------------------------------------------------------
__device__ __forceinline__ void ldsm_x4(uint32_t r[4], uint32_t addr) {
    asm volatile("ldmatrix.sync.aligned.m8n8.x4.shared.b16 {%0,%1,%2,%3}, [%4];"
                 : "=r"(r[0]), "=r"(r[1]), "=r"(r[2]), "=r"(r[3]) : "r"(addr));
}
__device__ __forceinline__ void ldsm_x4_t(uint32_t r[4], uint32_t addr) {
    asm volatile("ldmatrix.sync.aligned.m8n8.x4.trans.shared.b16 {%0,%1,%2,%3}, [%4];"
                 : "=r"(r[0]), "=r"(r[1]), "=r"(r[2]), "=r"(r[3]) : "r"(addr));
}
__device__ __forceinline__ void mma_bf16(float d[4], const uint32_t a[4],
                                         uint32_t b0, uint32_t b1) {
    asm volatile(
        "mma.sync.aligned.m16n8k16.row.col.f32.bf16.bf16.f32 "
        "{%0,%1,%2,%3}, {%4,%5,%6,%7}, {%8,%9}, {%0,%1,%2,%3};"
        : "+f"(d[0]), "+f"(d[1]), "+f"(d[2]), "+f"(d[3])
        : "r"(a[0]), "r"(a[1]), "r"(a[2]), "r"(a[3]), "r"(b0), "r"(b1));
}
__device__ __forceinline__ uint32_t pack_bf2(float a, float b) {
    __nv_bfloat162 t = __floats2bfloat162_rn(a, b);  // a -> low half
    return reinterpret_cast<uint32_t&>(t);
}
__device__ __forceinline__ float rcp_approx(float x) {
    float r;
    asm("rcp.approx.f32 %0, %1;" : "=f"(r) : "f"(x));
    return r;
}

// ---------------------------------------------------------------------------
// Kernel 1: fused elementwise + dual bf16 GEMM over a c-slab.
//   Register-prefetch pipeline (R11 config: occ=2, full reg headroom — the
//   occ=3 experiment in R12 capped regs at 85 and destroyed prefetch MLP).
//   grid = (kSlabs, 2 n-halves, kB), block = 256 (8 warps, 16 n each)
// ---------------------------------------------------------------------------
__global__ void __launch_bounds__(256, 2)
cost_main(const float* __restrict__ heat, const float* __restrict__ tgt) {
    const int slab  = blockIdx.x;
    const int nhalf = blockIdx.y;
    const int b     = blockIdx.z;
    const int t     = threadIdx.x;
    const int lane  = t & 31;
    const int warp  = t >> 5;

    // SMEM tiles (rows padded +16B for conflict-free ldmatrix)
    __shared__ __align__(16) __nv_bfloat16 sX[kKC][136];  // [c][n] (x)
    __shared__ __align__(16) __nv_bfloat16 sS[kKC][136];  // [c][n] (sig)
    __shared__ __align__(16) __nv_bfloat16 sT[kM][72];    // [m][c] (tgt)
    __shared__ __align__(16) float         red[8][32][4][2];

    // Accumulators
    float d[2][2][2][4];  // [qty x/s][m-tile][n8][frag]
#pragma unroll
    for (int q = 0; q < 2; ++q)
#pragma unroll
        for (int mt = 0; mt < 2; ++mt)
#pragma unroll
            for (int nn = 0; nn < 2; ++nn)
#pragma unroll
                for (int k = 0; k < 4; ++k) d[q][mt][nn][k] = 0.f;
    float sneg4[4] = {0.f, 0.f, 0.f, 0.f};
    float ssum4[4] = {0.f, 0.f, 0.f, 0.f};
    float tsum_loc = 0.f;

    // Staging maps
    const int col    = t & 31;      // float4 column group -> n_local = col*4..+3
    const int rowgrp = t >> 5;      // covers c rows rowgrp*8 .. rowgrp*8+7
    const float* Xg = heat + (size_t)b * kHW * kN + nhalf * 128 + col * 4;
    const int tm = t >> 3;          // tgt row m (0..31)
    const int tc = t & 7;
    const float* Tg = tgt + ((size_t)b * kM + tm) * kHW;

    const uint32_t sx_base = (uint32_t)__cvta_generic_to_shared(&sX[0][0]);
    const uint32_t ss_base = (uint32_t)__cvta_generic_to_shared(&sS[0][0]);
    const uint32_t st_base = (uint32_t)__cvta_generic_to_shared(&sT[0][0]);

    // ldmatrix per-lane address components
    const int sub = lane & 7, grp = lane >> 3;
    const int nw  = warp * 16;  // local n offset of this warp
    const uint32_t bB_off =
        ((((grp & 1) << 3) + sub) * 136 + nw + ((grp & 2) ? 8 : 0)) * 2;
    const uint32_t aoff0 =
        ((((grp & 1) << 3) + sub) * 72 + ((grp & 2) ? 8 : 0)) * 2;
    const uint32_t aoff1 = aoff0 + 16 * 72 * 2;

    // Prefetch registers (one set; convert drains them before the next LOAD)
    float4 hreg[8];
    float4 treg[2];

    // ---- prologue: load chunk 0
    {
        const int cbase = slab * kSlabC;
#pragma unroll
        for (int i = 0; i < 8; ++i)
            hreg[i] = *reinterpret_cast<const float4*>(
                Xg + (size_t)(cbase + rowgrp * 8 + i) * kN);
#pragma unroll
        for (int j = 0; j < 2; ++j)
            treg[j] = *reinterpret_cast<const float4*>(
                Tg + cbase + ((tc * 2 + j) << 2));
    }

#pragma unroll 1
    for (int ch = 0; ch < kChunks; ++ch) {
        // ---- convert current registers -> SMEM tiles (MUFU phase)
#pragma unroll
        for (int i = 0; i < 8; ++i) {
            const int cl = rowgrp * 8 + i;
            const float xv[4] = {hreg[i].x, hreg[i].y, hreg[i].z, hreg[i].w};
            float sv[4];
#pragma unroll
            for (int k = 0; k < 4; ++k) {
                const float x = xv[k];
                const float e = __expf(-fabsf(x));
                const float r = rcp_approx(1.f + e);
                const float s = (x >= 0.f) ? r : e * r;
                const float sp = fmaxf(x, 0.f) + __logf(1.f + e);  // softplus(x)
                sneg4[k] += sp;
                ssum4[k] += s;
                sv[k] = s;
            }
            uint2 ux, us;
            ux.x = pack_bf2(xv[0], xv[1]); ux.y = pack_bf2(xv[2], xv[3]);
            us.x = pack_bf2(sv[0], sv[1]); us.y = pack_bf2(sv[2], sv[3]);
            *reinterpret_cast<uint2*>(&sX[cl][col * 4]) = ux;
            *reinterpret_cast<uint2*>(&sS[cl][col * 4]) = us;
        }
#pragma unroll
        for (int j = 0; j < 2; ++j) {
            const int c0l = (tc * 2 + j) << 2;
            const float4 v = treg[j];
            tsum_loc += (v.x + v.y) + (v.z + v.w);
            uint2 ut;
            ut.x = pack_bf2(v.x, v.y); ut.y = pack_bf2(v.z, v.w);
            *reinterpret_cast<uint2*>(&sT[tm][c0l]) = ut;
        }
        __syncthreads();

        // ---- prefetch chunk ch+1 (front-batched LDGs; hidden under MMA)
        if (ch + 1 < kChunks) {
            const int cbase = slab * kSlabC + (ch + 1) * kKC;
#pragma unroll
            for (int i = 0; i < 8; ++i)
                hreg[i] = *reinterpret_cast<const float4*>(
                    Xg + (size_t)(cbase + rowgrp * 8 + i) * kN);
#pragma unroll
            for (int j = 0; j < 2; ++j)
                treg[j] = *reinterpret_cast<const float4*>(
                    Tg + cbase + ((tc * 2 + j) << 2));
        }

        // ---- MMA: 4 k-steps of 16 c
#pragma unroll
        for (int kk = 0; kk < 4; ++kk) {
            const uint32_t koff = kk * 16;
            uint32_t afr[2][4];
            ldsm_x4(afr[0], st_base + aoff0 + koff * 2);
            ldsm_x4(afr[1], st_base + aoff1 + koff * 2);
            uint32_t bx[4], bs[4];
            const uint32_t bo = koff * 136 * 2 + bB_off;
            ldsm_x4_t(bx, sx_base + bo);
            ldsm_x4_t(bs, ss_base + bo);
#pragma unroll
            for (int mt = 0; mt < 2; ++mt)
#pragma unroll
                for (int nn = 0; nn < 2; ++nn) {
                    mma_bf16(d[0][mt][nn], afr[mt], bx[2 * nn], bx[2 * nn + 1]);
                    mma_bf16(d[1][mt][nn], afr[mt], bs[2 * nn], bs[2 * nn + 1]);
                }
        }
        __syncthreads();
    }

    // ---- write GEMM partials: pX/pS [slab][b][m][n]
    {
        const int m0   = lane >> 2;
        const int ncol = (lane & 3) * 2;
#pragma unroll
        for (int q = 0; q < 2; ++q) {
            float* pb = (q ? g_pS : g_pX) + (size_t)(slab * kB + b) * kM * kN;
#pragma unroll
            for (int mt = 0; mt < 2; ++mt)
#pragma unroll
                for (int nn = 0; nn < 2; ++nn) {
                    const int n = nhalf * 128 + nw + nn * 8 + ncol;
                    const int m = mt * 16 + m0;
                    float2 v;
                    v.x = d[q][mt][nn][0]; v.y = d[q][mt][nn][1];
                    *reinterpret_cast<float2*>(&pb[m * kN + n]) = v;
                    v.x = d[q][mt][nn][2]; v.y = d[q][mt][nn][3];
                    *reinterpret_cast<float2*>(&pb[(m + 8) * kN + n]) = v;
                }
        }
    }

    // ---- tgt row-sum partials (8 lanes per m; deterministic shfl tree)
    {
        float v = tsum_loc;
        v += __shfl_xor_sync(0xffffffffu, v, 1);
        v += __shfl_xor_sync(0xffffffffu, v, 2);
        v += __shfl_xor_sync(0xffffffffu, v, 4);
        if (nhalf == 0 && tc == 0)
            g_ptsum[(slab * kB + b) * kM + tm] = v;
    }

    // ---- deterministic row-sum reduction across the 8 row-groups
#pragma unroll
    for (int k = 0; k < 4; ++k) {
        red[rowgrp][col][k][0] = sneg4[k];
        red[rowgrp][col][k][1] = ssum4[k];
    }
    __syncthreads();
    {
        const int ocol = t >> 3, osub = (t >> 1) & 3, q = t & 1;
        float acc = 0.f;
#pragma unroll
        for (int r = 0; r < 8; ++r) acc += red[r][ocol][osub][q];
        const int ngl = nhalf * 128 + ocol * 4 + osub;
        (q ? g_ssum : g_sneg)[(slab * kB + b) * kN + ngl] = acc;
    }
}

// ---------------------------------------------------------------------------
// Kernel 2: reduce slab partials + final cost assembly
//   thread -> (b, m, n): n fastest (coalesced partial reads)
//   Explicit 16-wide register batches force high MLP (proven: 21.7 -> 11.8us)
// ---------------------------------------------------------------------------
__global__ void __launch_bounds__(256)
cost_epilogue(const float* __restrict__ sem, const float* __restrict__ center,
              const int* __restrict__ lw, float* __restrict__ out) {
    // Label dtype detection: int64 {0,1} labels have all-zero odd 32-bit words.
    __shared__ int s_or;
    const int tid = threadIdx.x;
    if (tid == 0) s_or = 0;
    __syncthreads();
    if (tid < 128 && lw[2 * tid + 1] != 0) atomicOr(&s_or, 1);
    __syncthreads();
    const bool is64 = (s_or == 0);

    const int g = blockIdx.x * 256 + tid;
    const int n = g & 255;
    const int m = (g >> 8) & 31;
    const int b = g >> 13;

    const int base_p = (b * kM + m) * kN + n;   // + s*kB*kM*kN
    const int base_s = b * kN + n;              // + s*kB*kN
    const int stride_p = kB * kM * kN;
    const int stride_s = kB * kN;

    float xt = 0.f, st = 0.f, sn = 0.f, ss = 0.f, ts = 0.f;
    float va[16], vb[16];

    // pX in two fully-resident batches of 16 (MLP=16)
#pragma unroll
    for (int s = 0; s < 16; ++s) va[s] = g_pX[base_p + s * stride_p];
#pragma unroll
    for (int s = 0; s < 16; ++s) vb[s] = g_pX[base_p + (s + 16) * stride_p];
#pragma unroll
    for (int s = 0; s < 16; ++s) xt += va[s] + vb[s];
    // pS
#pragma unroll
    for (int s = 0; s < 16; ++s) va[s] = g_pS[base_p + s * stride_p];
#pragma unroll
    for (int s = 0; s < 16; ++s) vb[s] = g_pS[base_p + (s + 16) * stride_p];
#pragma unroll
    for (int s = 0; s < 16; ++s) st += va[s] + vb[s];
    // sneg
#pragma unroll
    for (int s = 0; s < 16; ++s) va[s] = g_sneg[base_s + s * stride_s];
#pragma unroll
    for (int s = 0; s < 16; ++s) vb[s] = g_sneg[base_s + (s + 16) * stride_s];
#pragma unroll
    for (int s = 0; s < 16; ++s) sn += va[s] + vb[s];
    // ssum
#pragma unroll
    for (int s = 0; s < 16; ++s) va[s] = g_ssum[base_s + s * stride_s];
#pragma unroll
    for (int s = 0; s < 16; ++s) vb[s] = g_ssum[base_s + (s + 16) * stride_s];
#pragma unroll
    for (int s = 0; s < 16; ++s) ss += va[s] + vb[s];
    // ptsum (broadcast within warp; L1-hot)
#pragma unroll
    for (int s = 0; s < kSlabs; ++s) ts += g_ptsum[(s * kB + b) * kM + m];

    const int li  = b * kM + m;
    const int lbl = is64 ? lw[2 * li] : lw[li];
    const float p = sem[b * kN + n];
    const float cls   = -(lbl ? p : (1.f - p));
    const float cd    = center[(b * kN + n) * kM + m];
    const float cmask = (sn - xt) * (1.f / (float)kHW);      // Sneg - x_tgt
    const float dice  = 1.f - (2.f * st + 1.f) / (ss + ts + 1.f);

    out[(b * kN + n) * kM + m] = 2.f * cls + cd + 5.f * cmask + 2.f * dice;
}

// ---------------------------------------------------------------------------
// Entry point
// Inputs: 0 sem_cls_prob [B,N,1] f32 | 1 center_dist [B,N,M] f32
//         2 mask_heatmaps [B,HW,N] f32 | 3 mask_tgt [B,M,HW] f32
//         4 gt_plane_sem_cls_label [B,M] int (32 or 64, auto-detected)
//         5 nactual_gt (unused)
// ---------------------------------------------------------------------------
extern "C" void kernel_launch(void* const* d_in, const int* in_sizes, int n_in,
                              void* d_out, int out_size) {
    (void)in_sizes; (void)n_in; (void)out_size;
    const float* sem    = (const float*)d_in[0];
    const float* center = (const float*)d_in[1];
    const float* heat   = (const float*)d_in[2];
    const float* tgt    = (const float*)d_in[3];
    const int*   lbl    = (const int*)d_in[4];
    float* out = (float*)d_out;

    dim3 g1(kSlabs, 2, kB);
    cost_main<<<g1, 256>>>(heat, tgt);
    cost_epilogue<<<(kB * kN * kM) / 256, 256>>>(sem, center, lbl, out);
}